// round 8
// baseline (speedup 1.0000x reference)
#include <cuda_runtime.h>
#include <cuda_bf16.h>
#include <cstdint>

#define LL 65536
#define DD 256
#define CC 1024     // chunks == blocks
#define RR 64       // rows per chunk

#define NEG_INF __int_as_float(0xff800000)

// ---- scratch (device globals) ----
__device__ float g_aM[CC], g_aU[CC];     // chunk aggregates (scalar)
__device__ float g_aW[CC * DD];          // chunk aggregate W (ref aM)
__device__ float g_iM[CC], g_iU[CC];     // inclusive prefixes (scalar)
__device__ float g_iW[CC * DD];          // inclusive prefix W (ref iM)
__device__ unsigned g_flag[CC];          // epoch*4 + {1=aggregate,2=inclusive}
__device__ unsigned g_ctr;               // epoch counter (monotonic)

__global__ __launch_bounds__(256, 8) void k_onepass(const float* __restrict__ K,
                                                    const float* __restrict__ V,
                                                    const float* __restrict__ q,
                                                    float* __restrict__ out) {
    __shared__ __align__(16) float q_sh[DD];
    __shared__ __align__(16) float wpart[4][DD];
    __shared__ float s_sh[RR], e_sh[RR], m_sh[RR];
    __shared__ float a_sh[RR], b_sh[RR], sA[RR], sB[RR], inv_sh[RR];
    __shared__ float red_sh[8];
    __shared__ float Mbc, Ubc;
    __shared__ unsigned ep_sh, st_sh;

    const int c = blockIdx.x;
    const int t = threadIdx.x;
    const int lane = t & 31;
    const int wid = t >> 5;

    if (t == 0) { ep_sh = atomicAdd(&g_ctr, 1u) / CC; }   // same epoch for all CC blocks
    q_sh[t] = q[t];
    __syncthreads();
    const unsigned eb = ep_sh * 4u;

    // ============ Phase A: s = K·q ============
    const float4* q4 = reinterpret_cast<const float4*>(q_sh);
    const float4* K4 = reinterpret_cast<const float4*>(K) + (size_t)c * RR * 64;

    float4 qa = q4[lane], qb = q4[32 + lane];
#pragma unroll
    for (int k = 0; k < RR / 8; k++) {
        int r = wid * (RR / 8) + k;
        float4 ka = __ldcs(&K4[r * 64 + lane]);      // K read-once: evict-first
        float4 kb = __ldcs(&K4[r * 64 + 32 + lane]);
        float p = ka.x * qa.x + ka.y * qa.y + ka.z * qa.z + ka.w * qa.w
                + kb.x * qb.x + kb.y * qb.y + kb.z * qb.z + kb.w * qb.w;
#pragma unroll
        for (int o = 16; o; o >>= 1) p += __shfl_xor_sync(0xffffffffu, p, o);
        if (lane == 0) s_sh[r] = p;
    }
    __syncthreads();

    // chunk max M
    float m = (t < RR) ? s_sh[t] : NEG_INF;
#pragma unroll
    for (int o = 16; o; o >>= 1) m = fmaxf(m, __shfl_xor_sync(0xffffffffu, m, o));
    if (lane == 0) red_sh[wid] = m;
    __syncthreads();
    if (t == 0) {
        float mm = NEG_INF;
#pragma unroll
        for (int w = 0; w < 8; w++) mm = fmaxf(mm, red_sh[w]);
        Mbc = mm;
    }
    __syncthreads();
    const float M = Mbc;

    if (t < RR) e_sh[t] = __expf(s_sh[t] - M);
    __syncthreads();

    // U = sum e
    float uu = (t < RR) ? e_sh[t] : 0.f;
#pragma unroll
    for (int o = 16; o; o >>= 1) uu += __shfl_xor_sync(0xffffffffu, uu, o);
    __syncthreads();
    if (lane == 0) red_sh[wid] = uu;
    __syncthreads();
    if (t == 0) {
        float U = 0.f;
#pragma unroll
        for (int w = 0; w < 8; w++) U += red_sh[w];
        Ubc = U;
        g_aM[c] = M;
        g_aU[c] = U;
    }

    // W[d] = sum_i e_i * V[i][d]  — V FIRST read (default policy: keep in L2)
    {
        const int grp = t >> 6;
        const int j = t & 63;
        const float4* V4 = reinterpret_cast<const float4*>(V) + (size_t)c * RR * 64;
        float4 acc = make_float4(0.f, 0.f, 0.f, 0.f);
#pragma unroll
        for (int i = grp; i < RR; i += 4) {
            float e = e_sh[i];
            float4 v = V4[i * 64 + j];
            acc.x += e * v.x; acc.y += e * v.y; acc.z += e * v.z; acc.w += e * v.w;
        }
        reinterpret_cast<float4*>(wpart[grp])[j] = acc;
    }
    __syncthreads();
    const float Wl = wpart[0][t] + wpart[1][t] + wpart[2][t] + wpart[3][t];
    g_aW[(size_t)c * DD + t] = Wl;

    // publish AGGREGATE (release)
    __threadfence();
    if (t == 0) atomicExch(&g_flag[c], eb + 1u);

    // in-chunk inclusive prefix max over s (independent of carry — do while others publish)
    if (t < RR) m_sh[t] = s_sh[t];
    __syncthreads();
    {
        float cmx = (t < RR) ? m_sh[t] : NEG_INF;
#pragma unroll
        for (int off = 1; off < RR; off <<= 1) {
            float v = NEG_INF;
            if (t < RR && t >= off) v = m_sh[t - off];
            __syncthreads();
            if (t < RR) { cmx = fmaxf(cmx, v); m_sh[t] = cmx; }
            __syncthreads();
        }
    }

    // ============ Lookback: accumulate carry over chunks [0, c) ============
    float car_w = 0.f, car_M = NEG_INF, car_U = 0.f;
    {
        int idx = c - 1;
        while (idx >= 0) {
            if (t == 0) {
                unsigned v;
                do {
                    asm volatile("ld.global.acquire.gpu.u32 %0, [%1];"
                                 : "=r"(v) : "l"(&g_flag[idx]));
                } while (v < eb + 1u);
                st_sh = v - eb;
            }
            __syncthreads();
            const int state = (int)st_sh;
            float Ma, Ua, Wa;
            if (state >= 2) {
                Ma = g_iM[idx]; Ua = g_iU[idx];
                Wa = __ldcg(&g_iW[(size_t)idx * DD + t]);
            } else {
                Ma = g_aM[idx]; Ua = g_aU[idx];
                Wa = __ldcg(&g_aW[(size_t)idx * DD + t]);
            }
            // prepend [idx] in front of carry
            float Mn = fmaxf(Ma, car_M);
            float ea = __expf(Ma - Mn);
            float ec = __expf(car_M - Mn);     // exp(-inf - finite) = 0 : safe
            car_w = fmaf(car_w, ec, Wa * ea);
            car_U = fmaf(car_U, ec, Ua * ea);
            car_M = Mn;
            __syncthreads();                   // st_sh reuse guard
            if (state >= 2) break;
            idx--;
        }
    }

    // publish INCLUSIVE = carry ∘ local aggregate
    {
        const float Ul = Ubc;
        float Mi = fmaxf(car_M, M);
        float el = __expf(M - Mi);
        float ec = __expf(car_M - Mi);
        g_iW[(size_t)c * DD + t] = fmaf(car_w, ec, Wl * el);
        if (t == 0) {
            g_iM[c] = Mi;
            g_iU[c] = fmaf(car_U, ec, Ul * el);
        }
        __threadfence();
        if (t == 0) atomicExch(&g_flag[c], eb + 2u);
    }

    // ============ Phase C: per-row recurrence, V re-read (L2-hot) ============
    const float Mp_c = car_M;
    const float Up_c = car_U;

    float cA = 1.f, cB = 0.f;
    if (t < RR) {
        float mi = fmaxf(m_sh[t], Mp_c);
        float mp = (t == 0) ? Mp_c : fmaxf(m_sh[t - 1], Mp_c);
        float a = __expf(mp - mi);
        float bb = __expf(s_sh[t] - mi);
        a_sh[t] = a; b_sh[t] = bb;
        cA = a; cB = bb;
        sA[t] = a; sB[t] = bb;
    }
    __syncthreads();

    // pair scan: u_i = B_i + A_i * Up_c
#pragma unroll
    for (int off = 1; off < RR; off <<= 1) {
        float va = 1.f, vb = 0.f;
        if (t < RR && t >= off) { va = sA[t - off]; vb = sB[t - off]; }
        __syncthreads();
        if (t < RR) {
            cB = fmaf(vb, cA, cB);
            cA = va * cA;
            sA[t] = cA; sB[t] = cB;
        }
        __syncthreads();
    }
    if (t < RR) inv_sh[t] = 1.0f / fmaf(cA, Up_c, cB);
    __syncthreads();

    float w = car_w;   // exclusive W prefix, ref Mp_c

    const float* Vb = V + (size_t)c * RR * DD + t;
    float* Ob = out + (size_t)c * RR * DD + t;

    float cur[8];
#pragma unroll
    for (int j = 0; j < 8; j++) cur[j] = __ldcs(&Vb[(size_t)j * DD]);  // last use: evict

    for (int ib = 0; ib < RR; ib += 8) {
        float nxt[8];
#pragma unroll
        for (int j = 0; j < 8; j++)
            nxt[j] = (ib + 8 < RR) ? __ldcs(&Vb[(size_t)(ib + 8 + j) * DD]) : 0.f;
#pragma unroll
        for (int j = 0; j < 8; j++) {
            int i = ib + j;
            w = fmaf(w, a_sh[i], b_sh[i] * cur[j]);
            __stcs(&Ob[(size_t)i * DD], w * inv_sh[i]);   // write-once: stream
        }
#pragma unroll
        for (int j = 0; j < 8; j++) cur[j] = nxt[j];
    }
}

// ============================================================
extern "C" void kernel_launch(void* const* d_in, const int* in_sizes, int n_in,
                              void* d_out, int out_size) {
    const float* K = (const float*)d_in[0];
    const float* V = (const float*)d_in[1];
    const float* q = (const float*)d_in[2];
    float* out = (float*)d_out;

    k_onepass<<<CC, 256>>>(K, V, q, out);
}

// round 9
// speedup vs baseline: 1.3202x; 1.3202x over previous
#include <cuda_runtime.h>
#include <cuda_bf16.h>
#include <cstdint>

#define LL 65536
#define DD 256
#define CC 1024     // number of chunks
#define RR 64       // rows per chunk
#define NSEG 32     // segments
#define SEGC 32     // chunks per segment (CC / NSEG)

#define NEG_INF __int_as_float(0xff800000)

// ---- scratch (device globals) ----
__device__ float g_s[LL];            // s[i] = K[i]·q
__device__ float g_M[CC], g_U[CC];   // per-chunk aggregates (U ref M)
__device__ float g_W[CC * DD];       // per-chunk vector aggregate (ref M_c)
__device__ float g_Mp[CC], g_Up[CC]; // exclusive prefix (Up ref Mp)
__device__ float g_Wp[CC * DD];      // segment-local exclusive W prefix (ref Mp_c)
__device__ float g_seg[NSEG * DD];   // segment aggregates (ref Mp[(b+1)*SEGC])

// ============================================================
// Pass 1: fully warp-local K-dot + V-accumulate (no block sync
// between the K and V streams), then one rescaling combine.
// Warp w owns rows 8w..8w+7. Lane owns dims lane*8..lane*8+7.
// ============================================================
__global__ __launch_bounds__(256, 8) void k_pass1(const float* __restrict__ K,
                                                  const float* __restrict__ V,
                                                  const float* __restrict__ q) {
    __shared__ __align__(16) float wp[8][DD];     // 8KB warp partial W (ref m_w)
    __shared__ float s_sh[RR];
    __shared__ float mw_sh[8], Uw_sh[8];

    const int c = blockIdx.x;
    const int t = threadIdx.x;
    const int lane = t & 31;
    const int wid = t >> 5;

    // lane's 8 q dims (2 float4)
    const float4* q4g = reinterpret_cast<const float4*>(q);
    float4 qa = q4g[lane * 2];
    float4 qb = q4g[lane * 2 + 1];

    const float4* K4 = reinterpret_cast<const float4*>(K) + (size_t)(c * RR + wid * 8) * 64;
    const float4* V4 = reinterpret_cast<const float4*>(V) + (size_t)(c * RR + wid * 8) * 64;

    // --- 8 K-row dots (warp-local) ---
    float pk[8];
#pragma unroll
    for (int k = 0; k < 8; k++) {
        float4 ka = __ldcs(&K4[k * 64 + lane * 2]);
        float4 kb = __ldcs(&K4[k * 64 + lane * 2 + 1]);
        float p = ka.x * qa.x + ka.y * qa.y + ka.z * qa.z + ka.w * qa.w
                + kb.x * qb.x + kb.y * qb.y + kb.z * qb.z + kb.w * qb.w;
#pragma unroll
        for (int o = 16; o; o >>= 1) p += __shfl_xor_sync(0xffffffffu, p, o);
        pk[k] = p;                         // all lanes hold the row dot
    }

    // warp-local max / e / U (each lane computes redundantly)
    float mw = NEG_INF;
#pragma unroll
    for (int k = 0; k < 8; k++) mw = fmaxf(mw, pk[k]);
    float ek[8];
    float Uw = 0.f;
#pragma unroll
    for (int k = 0; k < 8; k++) { ek[k] = __expf(pk[k] - mw); Uw += ek[k]; }

    // --- V accumulate (warp-local, starts immediately) ---
    float4 aa = make_float4(0.f, 0.f, 0.f, 0.f);
    float4 ab = make_float4(0.f, 0.f, 0.f, 0.f);
#pragma unroll
    for (int k = 0; k < 8; k++) {
        float4 va = V4[k * 64 + lane * 2];
        float4 vb = V4[k * 64 + lane * 2 + 1];
        float e = ek[k];
        aa.x = fmaf(e, va.x, aa.x); aa.y = fmaf(e, va.y, aa.y);
        aa.z = fmaf(e, va.z, aa.z); aa.w = fmaf(e, va.w, aa.w);
        ab.x = fmaf(e, vb.x, ab.x); ab.y = fmaf(e, vb.y, ab.y);
        ab.z = fmaf(e, vb.z, ab.z); ab.w = fmaf(e, vb.w, ab.w);
    }
    reinterpret_cast<float4*>(wp[wid])[lane * 2] = aa;
    reinterpret_cast<float4*>(wp[wid])[lane * 2 + 1] = ab;

    // publish warp scalars + s
    if (lane == 0) { mw_sh[wid] = mw; Uw_sh[wid] = Uw; }
#pragma unroll
    for (int k = 0; k < 8; k++)
        if (lane == k) s_sh[wid * 8 + k] = pk[k];
    __syncthreads();

    // --- combine 8 warp partials (rescale to block max) ---
    float M = NEG_INF;
#pragma unroll
    for (int w = 0; w < 8; w++) M = fmaxf(M, mw_sh[w]);

    float sc[8];
#pragma unroll
    for (int w = 0; w < 8; w++) sc[w] = __expf(mw_sh[w] - M);

    float W = 0.f;
#pragma unroll
    for (int w = 0; w < 8; w++) W = fmaf(sc[w], wp[w][t], W);
    g_W[(size_t)c * DD + t] = W;

    if (t == 0) {
        float U = 0.f;
#pragma unroll
        for (int w = 0; w < 8; w++) U = fmaf(sc[w], Uw_sh[w], U);
        g_M[c] = M;
        g_U[c] = U;
    }
    if (t < RR) g_s[c * RR + t] = s_sh[t];
}

// ============================================================
// Mid kernel: NSEG blocks. All-parallel scalar scans; block b
// does the register-resident segment W-scan for its chunks.
// ============================================================
__global__ __launch_bounds__(256) void k_mid() {
    __shared__ float Pm[CC];
    __shared__ float alsh[CC];
    __shared__ float gash[CC];
    __shared__ float As[CC];
    __shared__ float Bs[CC];

    const int b = blockIdx.x;
    const int t = threadIdx.x;

    float mv[4];
#pragma unroll
    for (int r = 0; r < 4; r++) {
        mv[r] = g_M[t + r * 256];
        Pm[t + r * 256] = mv[r];
    }
    __syncthreads();

    // inclusive prefix max (Hillis-Steele), 4 elems/thread
    float cm[4];
#pragma unroll
    for (int r = 0; r < 4; r++) cm[r] = mv[r];
    for (int off = 1; off < CC; off <<= 1) {
        float v[4];
#pragma unroll
        for (int r = 0; r < 4; r++) {
            int i = t + r * 256;
            v[r] = (i >= off) ? Pm[i - off] : NEG_INF;
        }
        __syncthreads();
#pragma unroll
        for (int r = 0; r < 4; r++) {
            cm[r] = fmaxf(cm[r], v[r]);
            Pm[t + r * 256] = cm[r];
        }
        __syncthreads();
    }

    float ca[4], cb[4];
#pragma unroll
    for (int r = 0; r < 4; r++) {
        int i = t + r * 256;
        float Minc = Pm[i];
        float Mp = (i == 0) ? NEG_INF : Pm[i - 1];
        float a = (i == 0) ? 0.f : __expf(Mp - Minc);
        float g = __expf(mv[r] - Minc);
        alsh[i] = a;
        gash[i] = g;
        ca[r] = a;
        cb[r] = g_U[i] * g;
        As[i] = ca[r];
        Bs[i] = cb[r];
        if (b == 0) g_Mp[i] = Mp;
    }
    __syncthreads();

    // inclusive pair scan for u
    for (int off = 1; off < CC; off <<= 1) {
        float va[4], vb[4];
#pragma unroll
        for (int r = 0; r < 4; r++) {
            int i = t + r * 256;
            if (i >= off) { va[r] = As[i - off]; vb[r] = Bs[i - off]; }
            else          { va[r] = 1.f;         vb[r] = 0.f; }
        }
        __syncthreads();
#pragma unroll
        for (int r = 0; r < 4; r++) {
            int i = t + r * 256;
            cb[r] = fmaf(vb[r], ca[r], cb[r]);
            ca[r] = va[r] * ca[r];
            As[i] = ca[r];
            Bs[i] = cb[r];
        }
        __syncthreads();
    }

    if (b == 0) {
#pragma unroll
        for (int r = 0; r < 4; r++) {
            int i = t + r * 256;
            g_Up[i] = (i == 0) ? 0.f : Bs[i - 1];   // exclusive, ref Mp_i
        }
    }

    // segment W-scan, register-resident
    const int j0 = b * SEGC;
    const float* Wsrc = g_W + (size_t)j0 * DD + t;
    float* Wdst = g_Wp + (size_t)j0 * DD + t;

    float wc[SEGC];
#pragma unroll
    for (int j = 0; j < SEGC; j++) wc[j] = Wsrc[(size_t)j * DD];

    float w = 0.f;
#pragma unroll
    for (int j = 0; j < SEGC; j++) {
        Wdst[(size_t)j * DD] = w;              // exclusive within segment, ref Mp_c
        w = fmaf(w, alsh[j0 + j], wc[j] * gash[j0 + j]);
    }
    g_seg[b * DD + t] = w;                     // ref Mp[(b+1)*SEGC]
}

// ============================================================
// Pass 2: rebuild per-row recurrence (all scans parallel),
// stream V -> out. Reverse chunk order for L2 reuse of V tail.
// ============================================================
__global__ __launch_bounds__(256, 8) void k_pass2(const float* __restrict__ V,
                                                  float* __restrict__ out) {
    __shared__ float s_loc[RR], m_sh[RR];
    __shared__ float a_sh[RR], b_sh[RR];
    __shared__ float sA[RR], sB[RR];
    __shared__ float inv_sh[RR];

    const int c = (CC - 1) - blockIdx.x;
    const int t = threadIdx.x;

    const float Mp_c = g_Mp[c];
    const float Up_c = g_Up[c];

    if (t < RR) {
        float sv = g_s[c * RR + t];
        s_loc[t] = sv;
        m_sh[t] = sv;
    }
    __syncthreads();

    // inclusive prefix max over s within the chunk
    float cmx = (t < RR) ? m_sh[t] : NEG_INF;
#pragma unroll
    for (int off = 1; off < RR; off <<= 1) {
        float v = NEG_INF;
        if (t < RR && t >= off) v = m_sh[t - off];
        __syncthreads();
        if (t < RR) { cmx = fmaxf(cmx, v); m_sh[t] = cmx; }
        __syncthreads();
    }

    float cA = 1.f, cB = 0.f;
    if (t < RR) {
        float mi = fmaxf(m_sh[t], Mp_c);
        float mp = (t == 0) ? Mp_c : fmaxf(m_sh[t - 1], Mp_c);
        float a = __expf(mp - mi);            // exp(-inf - finite) = 0 : safe
        float bb = __expf(s_loc[t] - mi);
        a_sh[t] = a;
        b_sh[t] = bb;
        cA = a; cB = bb;
        sA[t] = a; sB[t] = bb;
    }
    __syncthreads();

    // inclusive pair scan: u_i = B_i + A_i * Up_c
#pragma unroll
    for (int off = 1; off < RR; off <<= 1) {
        float va = 1.f, vb = 0.f;
        if (t < RR && t >= off) { va = sA[t - off]; vb = sB[t - off]; }
        __syncthreads();
        if (t < RR) {
            cB = fmaf(vb, cA, cB);
            cA = va * cA;
            sA[t] = cA; sB[t] = cB;
        }
        __syncthreads();
    }
    if (t < RR) inv_sh[t] = 1.0f / fmaf(cA, Up_c, cB);
    __syncthreads();

    // seed: segment-local exclusive prefix + reconstructed carry
    const int seg = c / SEGC;
    float w = g_Wp[(size_t)c * DD + t];
    if (seg > 0) {
        float car = 0.f;
        for (int sb = 0; sb < seg; sb++) {
            float sc = (sb == 0) ? 0.f
                     : __expf(g_Mp[sb * SEGC] - g_Mp[(sb + 1) * SEGC]);
            car = fmaf(car, sc, g_seg[sb * DD + t]);
        }
        // car is ref Mp[seg*SEGC]; rescale to Mp_c
        w = fmaf(car, __expf(g_Mp[seg * SEGC] - Mp_c), w);
    }

    const float* Vb = V + (size_t)c * RR * DD + t;
    float* Ob = out + (size_t)c * RR * DD + t;

    float cur[8];
#pragma unroll
    for (int j = 0; j < 8; j++) cur[j] = Vb[(size_t)j * DD];

    for (int ib = 0; ib < RR; ib += 8) {
        float nxt[8];
#pragma unroll
        for (int j = 0; j < 8; j++)
            nxt[j] = (ib + 8 < RR) ? Vb[(size_t)(ib + 8 + j) * DD] : 0.f;
#pragma unroll
        for (int j = 0; j < 8; j++) {
            int i = ib + j;
            w = fmaf(w, a_sh[i], b_sh[i] * cur[j]);
            __stcs(&Ob[(size_t)i * DD], w * inv_sh[i]);   // write-once: stream
        }
#pragma unroll
        for (int j = 0; j < 8; j++) cur[j] = nxt[j];
    }
}

// ============================================================
extern "C" void kernel_launch(void* const* d_in, const int* in_sizes, int n_in,
                              void* d_out, int out_size) {
    const float* K = (const float*)d_in[0];
    const float* V = (const float*)d_in[1];
    const float* q = (const float*)d_in[2];
    float* out = (float*)d_out;

    k_pass1<<<CC, 256>>>(K, V, q);
    k_mid<<<NSEG, 256>>>();
    k_pass2<<<CC, 256>>>(V, out);
}

// round 10
// speedup vs baseline: 1.6577x; 1.2557x over previous
#include <cuda_runtime.h>
#include <cuda_bf16.h>
#include <cstdint>

#define LL 65536
#define DD 256
#define CC 1024     // number of chunks
#define RR 64       // rows per chunk
#define NSEG 32     // segments
#define SEGC 32     // chunks per segment (CC / NSEG)

#define NEG_INF __int_as_float(0xff800000)

// ---- scratch (device globals) ----
__device__ float g_s[LL];            // s[i] = K[i]·q
__device__ float g_M[CC], g_U[CC];   // per-chunk aggregates (U ref M)
__device__ float g_W[CC * DD];       // per-chunk vector aggregate (ref M_c)
__device__ float g_Mp[CC], g_Up[CC]; // exclusive prefix (Up ref Mp)
__device__ float g_Wp[CC * DD];      // segment-local exclusive W prefix (ref Mp_c)
__device__ float g_seg[NSEG * DD];   // segment aggregates (ref Mp[(b+1)*SEGC])

// ============================================================
// Pass 1: s = K·q ; per-chunk (M, U, W) reduction.
// V prefetched into registers across the reduction bubble;
// reduction done by warp 0 only (64 expf total, 2 syncs).
// ============================================================
__global__ __launch_bounds__(256, 8) void k_pass1(const float* __restrict__ K,
                                                  const float* __restrict__ V,
                                                  const float* __restrict__ q) {
    __shared__ __align__(16) float q_sh[DD];
    __shared__ __align__(16) float wpart[4][DD];
    __shared__ float s_sh[RR];
    __shared__ float e_sh[RR];

    const int c = blockIdx.x;
    const int t = threadIdx.x;
    const int lane = t & 31;
    const int wid = t >> 5;

    q_sh[t] = q[t];
    __syncthreads();

    const float4* q4 = reinterpret_cast<const float4*>(q_sh);
    const float4* K4 = reinterpret_cast<const float4*>(K) + (size_t)c * RR * 64;

    // --- K-dot: 8 warps x 8 rows, one warp per row ---
    float4 qa = q4[lane], qb = q4[32 + lane];
#pragma unroll
    for (int k = 0; k < RR / 8; k++) {
        int r = wid * (RR / 8) + k;
        float4 ka = __ldcs(&K4[r * 64 + lane]);        // K read-once: evict-first
        float4 kb = __ldcs(&K4[r * 64 + 32 + lane]);
        float p = ka.x * qa.x + ka.y * qa.y + ka.z * qa.z + ka.w * qa.w
                + kb.x * qb.x + kb.y * qb.y + kb.z * qb.z + kb.w * qb.w;
#pragma unroll
        for (int o = 16; o; o >>= 1) p += __shfl_xor_sync(0xffffffffu, p, o);
        if (lane == 0) s_sh[r] = p;
    }
    __syncthreads();

    // --- prefetch first 4 V rows per thread (independent of reduction) ---
    const int grp = t >> 6;
    const int j = t & 63;
    const float4* V4 = reinterpret_cast<const float4*>(V) + (size_t)c * RR * 64;
    float4 v0 = V4[(grp +  0) * 64 + j];
    float4 v1 = V4[(grp +  4) * 64 + j];
    float4 v2 = V4[(grp +  8) * 64 + j];
    float4 v3 = V4[(grp + 12) * 64 + j];

    // --- warp 0: M, e, U (64 expf total) ---
    if (wid == 0) {
        float s0 = s_sh[lane], s1 = s_sh[32 + lane];
        float m = fmaxf(s0, s1);
#pragma unroll
        for (int o = 16; o; o >>= 1) m = fmaxf(m, __shfl_xor_sync(0xffffffffu, m, o));
        float e0 = __expf(s0 - m), e1 = __expf(s1 - m);
        e_sh[lane] = e0; e_sh[32 + lane] = e1;
        float u = e0 + e1;
#pragma unroll
        for (int o = 16; o; o >>= 1) u += __shfl_xor_sync(0xffffffffu, u, o);
        if (lane == 0) { g_M[c] = m; g_U[c] = u; }
    }
    if (t < RR) g_s[c * RR + t] = s_sh[t];
    __syncthreads();

    // --- V accumulate: consume prefetched batch, then stream the rest ---
    float4 acc;
    {
        float e0 = e_sh[grp], e1 = e_sh[grp + 4], e2 = e_sh[grp + 8], e3 = e_sh[grp + 12];
        acc.x = e0 * v0.x + e1 * v1.x + e2 * v2.x + e3 * v3.x;
        acc.y = e0 * v0.y + e1 * v1.y + e2 * v2.y + e3 * v3.y;
        acc.z = e0 * v0.z + e1 * v1.z + e2 * v2.z + e3 * v3.z;
        acc.w = e0 * v0.w + e1 * v1.w + e2 * v2.w + e3 * v3.w;
    }
#pragma unroll
    for (int i = grp + 16; i < RR; i += 4) {
        float e = e_sh[i];
        float4 v = V4[i * 64 + j];
        acc.x = fmaf(e, v.x, acc.x); acc.y = fmaf(e, v.y, acc.y);
        acc.z = fmaf(e, v.z, acc.z); acc.w = fmaf(e, v.w, acc.w);
    }
    reinterpret_cast<float4*>(wpart[grp])[j] = acc;
    __syncthreads();
    g_W[(size_t)c * DD + t] = wpart[0][t] + wpart[1][t] + wpart[2][t] + wpart[3][t];
}

// ============================================================
// Mid kernel: NSEG blocks. All-parallel scalar scans; block b
// does the register-resident segment W-scan for its chunks.
// ============================================================
__global__ __launch_bounds__(256) void k_mid() {
    __shared__ float Pm[CC];
    __shared__ float alsh[CC];
    __shared__ float gash[CC];
    __shared__ float As[CC];
    __shared__ float Bs[CC];

    const int b = blockIdx.x;
    const int t = threadIdx.x;

    float mv[4];
#pragma unroll
    for (int r = 0; r < 4; r++) {
        mv[r] = g_M[t + r * 256];
        Pm[t + r * 256] = mv[r];
    }
    __syncthreads();

    // inclusive prefix max (Hillis-Steele), 4 elems/thread
    float cm[4];
#pragma unroll
    for (int r = 0; r < 4; r++) cm[r] = mv[r];
    for (int off = 1; off < CC; off <<= 1) {
        float v[4];
#pragma unroll
        for (int r = 0; r < 4; r++) {
            int i = t + r * 256;
            v[r] = (i >= off) ? Pm[i - off] : NEG_INF;
        }
        __syncthreads();
#pragma unroll
        for (int r = 0; r < 4; r++) {
            cm[r] = fmaxf(cm[r], v[r]);
            Pm[t + r * 256] = cm[r];
        }
        __syncthreads();
    }

    float ca[4], cb[4];
#pragma unroll
    for (int r = 0; r < 4; r++) {
        int i = t + r * 256;
        float Minc = Pm[i];
        float Mp = (i == 0) ? NEG_INF : Pm[i - 1];
        float a = (i == 0) ? 0.f : __expf(Mp - Minc);
        float g = __expf(mv[r] - Minc);
        alsh[i] = a;
        gash[i] = g;
        ca[r] = a;
        cb[r] = g_U[i] * g;
        As[i] = ca[r];
        Bs[i] = cb[r];
        if (b == 0) g_Mp[i] = Mp;
    }
    __syncthreads();

    // inclusive pair scan for u
    for (int off = 1; off < CC; off <<= 1) {
        float va[4], vb[4];
#pragma unroll
        for (int r = 0; r < 4; r++) {
            int i = t + r * 256;
            if (i >= off) { va[r] = As[i - off]; vb[r] = Bs[i - off]; }
            else          { va[r] = 1.f;         vb[r] = 0.f; }
        }
        __syncthreads();
#pragma unroll
        for (int r = 0; r < 4; r++) {
            int i = t + r * 256;
            cb[r] = fmaf(vb[r], ca[r], cb[r]);
            ca[r] = va[r] * ca[r];
            As[i] = ca[r];
            Bs[i] = cb[r];
        }
        __syncthreads();
    }

    if (b == 0) {
#pragma unroll
        for (int r = 0; r < 4; r++) {
            int i = t + r * 256;
            g_Up[i] = (i == 0) ? 0.f : Bs[i - 1];   // exclusive, ref Mp_i
        }
    }

    // segment W-scan, register-resident
    const int j0 = b * SEGC;
    const float* Wsrc = g_W + (size_t)j0 * DD + t;
    float* Wdst = g_Wp + (size_t)j0 * DD + t;

    float wc[SEGC];
#pragma unroll
    for (int j = 0; j < SEGC; j++) wc[j] = Wsrc[(size_t)j * DD];

    float w = 0.f;
#pragma unroll
    for (int j = 0; j < SEGC; j++) {
        Wdst[(size_t)j * DD] = w;              // exclusive within segment, ref Mp_c
        w = fmaf(w, alsh[j0 + j], wc[j] * gash[j0 + j]);
    }
    g_seg[b * DD + t] = w;                     // ref Mp[(b+1)*SEGC]
}

// ============================================================
// Pass 2: per-row recurrence, stream V -> out.
// V cur[8] loaded at kernel ENTRY (hides the scan preamble);
// segment carry via precomputed scalar factors (telescoped).
// Reverse chunk order for L2 reuse of pass1's V tail.
// ============================================================
__global__ __launch_bounds__(256, 8) void k_pass2(const float* __restrict__ V,
                                                  float* __restrict__ out) {
    __shared__ float s_loc[RR], m_sh[RR];
    __shared__ float a_sh[RR], b_sh[RR];
    __shared__ float sA[RR], sB[RR];
    __shared__ float inv_sh[RR];
    __shared__ float fac_sh[NSEG];

    const int c = (CC - 1) - blockIdx.x;
    const int t = threadIdx.x;

    const float* Vb = V + (size_t)c * RR * DD + t;
    float* Ob = out + (size_t)c * RR * DD + t;

    // --- V prefetch at entry: independent of everything below ---
    float cur[8];
#pragma unroll
    for (int j = 0; j < 8; j++) cur[j] = Vb[(size_t)j * DD];

    const float Mp_c = g_Mp[c];
    const float Up_c = g_Up[c];
    const int seg = c / SEGC;

    if (t < RR) {
        float sv = g_s[c * RR + t];
        s_loc[t] = sv;
        m_sh[t] = sv;
    }
    // telescoped carry factors: fac[sb] = exp(Mp[(sb+1)*SEGC] - Mp_c), sb < seg
    if (t < seg) fac_sh[t] = __expf(g_Mp[(t + 1) * SEGC] - Mp_c);
    __syncthreads();

    // seed: w = Wp_c + sum_sb g_seg[sb][t] * fac[sb]  (independent loads)
    float w = g_Wp[(size_t)c * DD + t];
#pragma unroll 4
    for (int sb = 0; sb < seg; sb++)
        w = fmaf(__ldcg(&g_seg[sb * DD + t]), fac_sh[sb], w);

    // inclusive prefix max over s within the chunk
    float cmx = (t < RR) ? m_sh[t] : NEG_INF;
#pragma unroll
    for (int off = 1; off < RR; off <<= 1) {
        float v = NEG_INF;
        if (t < RR && t >= off) v = m_sh[t - off];
        __syncthreads();
        if (t < RR) { cmx = fmaxf(cmx, v); m_sh[t] = cmx; }
        __syncthreads();
    }

    float cA = 1.f, cB = 0.f;
    if (t < RR) {
        float mi = fmaxf(m_sh[t], Mp_c);
        float mp = (t == 0) ? Mp_c : fmaxf(m_sh[t - 1], Mp_c);
        float a = __expf(mp - mi);            // exp(-inf - finite) = 0 : safe
        float bb = __expf(s_loc[t] - mi);
        a_sh[t] = a;
        b_sh[t] = bb;
        cA = a; cB = bb;
        sA[t] = a; sB[t] = bb;
    }
    __syncthreads();

    // inclusive pair scan: u_i = B_i + A_i * Up_c
#pragma unroll
    for (int off = 1; off < RR; off <<= 1) {
        float va = 1.f, vb = 0.f;
        if (t < RR && t >= off) { va = sA[t - off]; vb = sB[t - off]; }
        __syncthreads();
        if (t < RR) {
            cB = fmaf(vb, cA, cB);
            cA = va * cA;
            sA[t] = cA; sB[t] = cB;
        }
        __syncthreads();
    }
    if (t < RR) inv_sh[t] = 1.0f / fmaf(cA, Up_c, cB);
    __syncthreads();

    // --- stream: w recurrence over 64 rows, double-buffered ---
    for (int ib = 0; ib < RR; ib += 8) {
        float nxt[8];
#pragma unroll
        for (int j = 0; j < 8; j++)
            nxt[j] = (ib + 8 < RR) ? Vb[(size_t)(ib + 8 + j) * DD] : 0.f;
#pragma unroll
        for (int j = 0; j < 8; j++) {
            int i = ib + j;
            w = fmaf(w, a_sh[i], b_sh[i] * cur[j]);
            __stcs(&Ob[(size_t)i * DD], w * inv_sh[i]);   // write-once: stream
        }
#pragma unroll
        for (int j = 0; j < 8; j++) cur[j] = nxt[j];
    }
}

// ============================================================
extern "C" void kernel_launch(void* const* d_in, const int* in_sizes, int n_in,
                              void* d_out, int out_size) {
    const float* K = (const float*)d_in[0];
    const float* V = (const float*)d_in[1];
    const float* q = (const float*)d_in[2];
    float* out = (float*)d_out;

    k_pass1<<<CC, 256>>>(K, V, q);
    k_mid<<<NSEG, 256>>>();
    k_pass2<<<CC, 256>>>(V, out);
}